// round 1
// baseline (speedup 1.0000x reference)
#include <cuda_runtime.h>
#include <math.h>

// ---------------------------------------------------------------------------
// ModelSimple: conv4d(1->5,k7) + ReLU -> conv4d(5->10,k7) + ReLU
//              -> flatten -> Linear(12960->1) -> sigmoid
// x:  [128,1,18,18,18,18]  f32
// w1: [5,1,7,7,7,7] b1:[5]
// w2: [10,5,7,7,7,7] b2:[10]
// w_lin: [1,12960] b_lin:[1]
// out: [128,1] f32
// ---------------------------------------------------------------------------

#define NB 128

// Intermediates (no cudaMalloc allowed): h1 = 128*5*20736 f32 (~53MB),
// h2 = 128*10*1296 f32 (~6.6MB)
__device__ float g_h1[NB * 5 * 20736];
__device__ float g_h2[NB * 10 * 1296];

// ---------------------------------------------------------------------------
// conv1: one block per (b, oh). Input slab x[b, oh:oh+7, :, :, :] is a
// contiguous 7*18*18*18 = 40824-float chunk -> SMEM. All weights (5*2401)
// also in SMEM. 288 threads: tid -> (ow, od, ot-half); each thread holds
// acc[5 oc][6 ot] in registers.
// ---------------------------------------------------------------------------
__global__ __launch_bounds__(288, 1)
void conv1_kernel(const float* __restrict__ x,
                  const float* __restrict__ w1,
                  const float* __restrict__ b1)
{
    extern __shared__ float sm1[];
    float* xs = sm1;            // 40824 floats
    float* ws = sm1 + 40824;    // 12005 floats

    const int blk = blockIdx.x;
    const int b  = blk / 12;
    const int oh = blk % 12;

    const float* xb = x + (size_t)b * 104976 + (size_t)oh * 5832;
    for (int i = threadIdx.x; i < 40824; i += 288) xs[i] = xb[i];
    for (int i = threadIdx.x; i < 12005; i += 288) ws[i] = w1[i];
    __syncthreads();

    const int tid = threadIdx.x;
    const int ow  = tid / 24;          // 0..11
    const int rem = tid % 24;
    const int od  = rem >> 1;          // 0..11
    const int ot0 = (rem & 1) * 6;     // 0 or 6

    float acc[5][6];
#pragma unroll
    for (int c = 0; c < 5; c++)
#pragma unroll
        for (int t = 0; t < 6; t++) acc[c][t] = 0.f;

    for (int kh = 0; kh < 7; kh++) {
        for (int kw = 0; kw < 7; kw++) {
#pragma unroll
            for (int kd = 0; kd < 7; kd++) {
                const float* xp = xs + (((kh * 18) + (ow + kw)) * 18 + (od + kd)) * 18 + ot0;
                float xr[12];
#pragma unroll
                for (int i = 0; i < 12; i++) xr[i] = xp[i];
                const int wbase = ((kh * 7 + kw) * 7 + kd) * 7;
#pragma unroll
                for (int kt = 0; kt < 7; kt++) {
#pragma unroll
                    for (int oc = 0; oc < 5; oc++) {
                        const float w = ws[oc * 2401 + wbase + kt];
#pragma unroll
                        for (int ot = 0; ot < 6; ot++)
                            acc[oc][ot] = fmaf(w, xr[ot + kt], acc[oc][ot]);
                    }
                }
            }
        }
    }

    // h1 layout: [b][oc][oh][ow][od][ot]
    const size_t obase = (size_t)b * 103680 + (size_t)oh * 1728
                       + (size_t)ow * 144 + (size_t)od * 12 + ot0;
#pragma unroll
    for (int oc = 0; oc < 5; oc++) {
        const float bias = b1[oc];
#pragma unroll
        for (int ot = 0; ot < 6; ot++) {
            float v = acc[oc][ot] + bias;
            g_h1[obase + (size_t)oc * 20736 + ot] = v > 0.f ? v : 0.f;
        }
    }
}

// ---------------------------------------------------------------------------
// conv2: one block per batch. Loop over ic: stage full 12^4 channel volume
// (20736 f) + that ic's 10x2401 weights in SMEM. 432 threads:
// tid -> (oh, ow, od, oc-half); each thread holds acc[5 oc][6 ot].
// ---------------------------------------------------------------------------
__global__ __launch_bounds__(432, 1)
void conv2_kernel(const float* __restrict__ w2,
                  const float* __restrict__ b2)
{
    extern __shared__ float sm2[];
    float* xs = sm2;            // 20736 floats
    float* ws = sm2 + 20736;    // 24010 floats

    const int b   = blockIdx.x;
    const int tid = threadIdx.x;
    const int t2  = tid >> 1;          // 0..215
    const int oh  = t2 / 36;           // 0..5
    const int ow  = (t2 / 6) % 6;      // 0..5
    const int od  = t2 % 6;            // 0..5
    const int oc0 = (tid & 1) * 5;     // 0 or 5

    float acc[5][6];
#pragma unroll
    for (int c = 0; c < 5; c++)
#pragma unroll
        for (int t = 0; t < 6; t++) acc[c][t] = 0.f;

    for (int ic = 0; ic < 5; ic++) {
        __syncthreads();   // prior iteration's reads done before overwrite
        const float* hb = g_h1 + ((size_t)b * 5 + ic) * 20736;
        for (int i = tid; i < 20736; i += 432) xs[i] = hb[i];
        for (int i = tid; i < 24010; i += 432) {
            const int oc  = i / 2401;
            const int tap = i - oc * 2401;
            ws[i] = w2[((size_t)oc * 5 + ic) * 2401 + tap];
        }
        __syncthreads();

        for (int kh = 0; kh < 7; kh++) {
            for (int kw = 0; kw < 7; kw++) {
#pragma unroll
                for (int kd = 0; kd < 7; kd++) {
                    const float* xp = xs + (((oh + kh) * 12 + (ow + kw)) * 12 + (od + kd)) * 12;
                    float xr[12];
#pragma unroll
                    for (int i = 0; i < 12; i++) xr[i] = xp[i];
                    const int wbase = ((kh * 7 + kw) * 7 + kd) * 7;
#pragma unroll
                    for (int kt = 0; kt < 7; kt++) {
#pragma unroll
                        for (int oc = 0; oc < 5; oc++) {
                            const float w = ws[(oc0 + oc) * 2401 + wbase + kt];
#pragma unroll
                            for (int ot = 0; ot < 6; ot++)
                                acc[oc][ot] = fmaf(w, xr[ot + kt], acc[oc][ot]);
                        }
                    }
                }
            }
        }
    }

    // h2 layout: [b][oc][oh][ow][od][ot]
    const size_t obase = (size_t)b * 12960 + (size_t)oh * 216
                       + (size_t)ow * 36 + (size_t)od * 6;
#pragma unroll
    for (int oc = 0; oc < 5; oc++) {
        const float bias = b2[oc0 + oc];
#pragma unroll
        for (int ot = 0; ot < 6; ot++) {
            float v = acc[oc][ot] + bias;
            g_h2[obase + (size_t)(oc0 + oc) * 1296 + ot] = v > 0.f ? v : 0.f;
        }
    }
}

// ---------------------------------------------------------------------------
// linear + sigmoid: one block per batch row, dot over 12960 + reduce.
// ---------------------------------------------------------------------------
__global__ __launch_bounds__(256)
void linear_kernel(const float* __restrict__ wl,
                   const float* __restrict__ bl,
                   float* __restrict__ out)
{
    const int b = blockIdx.x;
    const float* h = g_h2 + (size_t)b * 12960;
    float s = 0.f;
    for (int i = threadIdx.x; i < 12960; i += 256)
        s = fmaf(h[i], wl[i], s);

    __shared__ float red[8];
#pragma unroll
    for (int o = 16; o; o >>= 1) s += __shfl_xor_sync(0xFFFFFFFFu, s, o);
    if ((threadIdx.x & 31) == 0) red[threadIdx.x >> 5] = s;
    __syncthreads();
    if (threadIdx.x < 32) {
        s = (threadIdx.x < 8) ? red[threadIdx.x] : 0.f;
#pragma unroll
        for (int o = 4; o; o >>= 1) s += __shfl_xor_sync(0xFFFFFFFFu, s, o);
        if (threadIdx.x == 0) {
            const float z = s + bl[0];
            out[b] = 1.f / (1.f + expf(-z));
        }
    }
}

// ---------------------------------------------------------------------------
extern "C" void kernel_launch(void* const* d_in, const int* in_sizes, int n_in,
                              void* d_out, int out_size)
{
    const float* x    = (const float*)d_in[0];
    const float* w1   = (const float*)d_in[1];
    const float* b1   = (const float*)d_in[2];
    const float* w2   = (const float*)d_in[3];
    const float* b2   = (const float*)d_in[4];
    const float* wlin = (const float*)d_in[5];
    const float* blin = (const float*)d_in[6];
    float* out = (float*)d_out;

    const size_t smem1 = (40824 + 12005) * sizeof(float);  // ~206.4 KB
    const size_t smem2 = (20736 + 24010) * sizeof(float);  // ~174.8 KB
    cudaFuncSetAttribute(conv1_kernel, cudaFuncAttributeMaxDynamicSharedMemorySize, (int)smem1);
    cudaFuncSetAttribute(conv2_kernel, cudaFuncAttributeMaxDynamicSharedMemorySize, (int)smem2);

    conv1_kernel<<<NB * 12, 288, smem1>>>(x, w1, b1);
    conv2_kernel<<<NB, 432, smem2>>>(w2, b2);
    linear_kernel<<<NB, 256>>>(wlin, blin, out);
}